// round 9
// baseline (speedup 1.0000x reference)
#include <cuda_runtime.h>
#include <cuda_bf16.h>
#include <math.h>
#include <stdint.h>

// Problem constants (fixed by setup_inputs)
constexpr int B  = 4;
constexpr int H  = 256;
constexpr int W  = 256;
constexpr int C  = 256;
constexpr int K  = 1024;
constexpr int NP = 25;    // 5x5 window
constexpr int NPTS = B * K;

// Persistent-CTA config: single wave on GB300 (152 SMs x 4 CTAs).
constexpr int GRID = 608;

// Dynamic smem layout (53.4 KB -> 4 CTAs/SM):
//   [0]        uint64_t mbar[2]
//   [16]       float win[2][NP][C]        (2 x 25.6 KB ring)
//   [16+51200] float part0[256], part1[256]
//   [..]       float corr[NP]
constexpr int SMEM_MBAR  = 0;
constexpr int SMEM_WIN   = 16;
constexpr int SMEM_PART0 = SMEM_WIN + 2 * NP * C * 4;     // 51216
constexpr int SMEM_PART1 = SMEM_PART0 + 256 * 4;
constexpr int SMEM_CORR  = SMEM_PART1 + 256 * 4;
constexpr int SMEM_TOTAL = SMEM_CORR + NP * 4 + 16;       // ~53.4 KB

// Mathematical reduction of the reference (validated R5-R8: rel_err 1.49e-8):
//   Attention messages are broadcast-constant along the window axis n; every
//   consumer applies a softmax over n (shift-invariant) -> both layers and
//   Wq/Wk/Wv/Wo cancel exactly.
//   Output = pos + softmax_n(corr[n]) . offsets, with
//     corr[n] = sum_{g in [256n,256n+256)} win[g] * s[g & 255],
//   win[g] (g = ch*25 + p) the channel-scrambled window gather and
//   s[ch] = win_row12[ch] (window center).
//
// R8 lesson: per-point CTAs serialize TMA-wait -> compute; nothing saturates
// (DRAM 49%, issue 49%). This version: persistent CTAs, double-buffered TMA
// prefetch of the NEXT point's 25 x 1KB rows while computing the current one.

__device__ __forceinline__ uint32_t smem_u32(const void* p) {
    return (uint32_t)__cvta_generic_to_shared(p);
}

extern __shared__ __align__(16) char smem_raw[];

__global__ __launch_bounds__(256, 4)
void fine_match_kernel(const float* __restrict__ T,
                       const float* __restrict__ pos,
                       float* __restrict__ out,
                       int n_points) {
    uint64_t* mbar  = (uint64_t*)(smem_raw + SMEM_MBAR);
    float*    winb  = (float*)(smem_raw + SMEM_WIN);      // [2][NP][C]
    float*    part0 = (float*)(smem_raw + SMEM_PART0);
    float*    part1 = (float*)(smem_raw + SMEM_PART1);
    float*    corr  = (float*)(smem_raw + SMEM_CORR);

    const int t = threadIdx.x;

    if (t < 2) {
        asm volatile("mbarrier.init.shared.b64 [%0], 1;"
                     :: "r"(smem_u32(&mbar[t])) : "memory");
    }
    __syncthreads();

    // ---- TMA issue helper (warp 0 only; 25 rows of 1 KB each) ----
    auto issue = [&](int bk, int buf) {
        // all of warp 0 enters; t < 32 guaranteed by caller
        const int bb = bk >> 10;
        const float qr = __ldg(&pos[bk * 2 + 0]);
        const float qc = __ldg(&pos[bk * 2 + 1]);
        const int r = (int)qr, c = (int)qc;
        const int p = t;
        const int rr = r - 2 + p / 5;
        const int cc = c - 2 + p % 5;
        const bool valid = (t < NP) & (rr >= 0) & (rr < H) & (cc >= 0) & (cc < W);
        const unsigned vmask = __ballot_sync(0xffffffffu, valid);
        const uint32_t mb = smem_u32(&mbar[buf]);
        if (t == 0) {
            const uint32_t txbytes = (uint32_t)__popc(vmask) * (C * 4);
            asm volatile("mbarrier.arrive.expect_tx.shared.b64 _, [%0], %1;"
                         :: "r"(mb), "r"(txbytes) : "memory");
        }
        __syncwarp();
        if (valid) {
            const char* src = (const char*)T +
                ((size_t)bb * H * W + (size_t)rr * W + cc) * (C * 4);
            asm volatile(
                "cp.async.bulk.shared::cta.global.mbarrier::complete_tx::bytes "
                "[%0], [%1], %2, [%3];"
                :: "r"(smem_u32(&winb[(buf * NP + p) * C])), "l"(src),
                   "r"(C * 4), "r"(mb)
                : "memory");
        }
    };

    // ---- Prologue: prefetch this CTA's first point ----
    if (blockIdx.x < n_points && t < 32) issue(blockIdx.x, 0);

    int it = 0;
    for (int bk = blockIdx.x; bk < n_points; bk += GRID, ++it) {
        const int cur = it & 1;

        // Prefetch the next point into the other buffer (its previous
        // consumer finished before the loop-end barrier of iteration it-1).
        if (bk + GRID < n_points && t < 32) issue(bk + GRID, cur ^ 1);

        const float pr = pos[bk * 2 + 0];
        const float pc = pos[bk * 2 + 1];
        const int r = (int)pr, c = (int)pc;

        // ---- Wait for this point's gather (acquire orders smem reads) ----
        {
            const uint32_t mb = smem_u32(&mbar[cur]);
            const uint32_t parity = (uint32_t)((it >> 1) & 1);
            uint32_t done;
            do {
                asm volatile(
                    "{\n\t.reg .pred p;\n\t"
                    "mbarrier.try_wait.parity.acquire.cta.shared::cta.b64 p, [%1], %2, 0x989680;\n\t"
                    "selp.b32 %0, 1, 0, p;\n\t}"
                    : "=r"(done) : "r"(mb), "r"(parity) : "memory");
            } while (!done);
        }

        float* win = winb + cur * NP * C;   // [NP][C]

        // ---- Zero stale out-of-range rows (border points only; each thread
        //      zeroes exactly the elements it will read: win[p][t]) ----
        if (r < 2 || r > H - 3 || c < 2 || c > W - 3) {
            #pragma unroll
            for (int p = 0; p < NP; ++p) {
                const int rr = r - 2 + p / 5;
                const int cc = c - 2 + p % 5;
                if (rr < 0 || rr >= H || cc < 0 || cc >= W)
                    win[p * C + t] = 0.0f;
            }
        }

        // ---- Per-thread partial dot (thread t owns channel t of all rows) ----
        // g = t*25 + p; s[g&255] = win[12][.]; bin n = g>>8 spans <= 2.
        const int g0 = t * NP;
        const int m0 = g0 & (C - 1);
        const int ps = C - m0;
        float a0 = 0.0f, a1 = 0.0f;
        #pragma unroll
        for (int p = 0; p < NP; ++p) {
            // win[p][t]: lane-consecutive; win[12][.]: stride 25 -> both conflict-free
            const int sidx = (p < ps) ? (m0 + p) : (m0 + p - C);
            const float f = win[p * C + t] * win[12 * C + sidx];
            if (p < ps) a0 += f; else a1 += f;
        }
        part0[t] = a0;
        part1[t] = a1;
        __syncthreads();

        // ---- Deterministic segmented reduction over the 25 bins ----
        if (t < NP) {
            const int n    = t;
            const int t_lo = (256 * n) / 25;
            const int t_hi = min(255, (256 * n + 255) / 25);
            float acc = 0.0f;
            for (int tt = t_lo; tt <= t_hi; ++tt)
                acc += (((tt * NP) >> 8) == n) ? part0[tt] : part1[tt];
            corr[n] = acc;
        }
        __syncwarp();

        // ---- Softmax over 25 logits + expectation over offsets (warp 0) ----
        if (t < 32) {
            const bool valid = (t < NP);
            float lv = valid ? corr[t] : -INFINITY;
            float m = lv;
            #pragma unroll
            for (int o = 16; o; o >>= 1)
                m = fmaxf(m, __shfl_xor_sync(0xffffffffu, m, o));
            float e = valid ? expf(lv - m) : 0.0f;
            float sum = e;
            #pragma unroll
            for (int o = 16; o; o >>= 1)
                sum += __shfl_xor_sync(0xffffffffu, sum, o);

            // off1d = linspace(-3, 2, 5) = -3 + 1.25*idx (faithful -w//2 = -3)
            float ox = 0.0f, oy = 0.0f;
            if (valid) {
                ox = -3.0f + 1.25f * (float)(t / 5);
                oy = -3.0f + 1.25f * (float)(t % 5);
            }
            float dx = e * ox;
            float dy = e * oy;
            #pragma unroll
            for (int o = 16; o; o >>= 1) {
                dx += __shfl_xor_sync(0xffffffffu, dx, o);
                dy += __shfl_xor_sync(0xffffffffu, dy, o);
            }
            if (t == 0) {
                const float inv = 1.0f / sum;
                out[bk * 2 + 0] = pr + dx * inv;
                out[bk * 2 + 1] = pc + dy * inv;
            }
        }
        __syncthreads();   // all reads of this buffer + part/corr done before reuse
    }
}

extern "C" void kernel_launch(void* const* d_in, const int* in_sizes, int n_in,
                              void* d_out, int out_size) {
    // metadata order: source_features, target_features, coarse_positions,
    //                 Wq, Wk, Wv, Wo.
    // source_features and all weight matrices are provably unused (softmax
    // shift-invariance eliminates the attention layers entirely).
    const float* target = (const float*)d_in[1];
    const float* pos    = (const float*)d_in[2];
    float* out          = (float*)d_out;

    const int n_points = in_sizes[2] / 2;   // B*K = 4096 for the pinned shape

    // Host-side attribute set (not a stream op; graph-capture safe).
    static bool attr_done = false;
    if (!attr_done) {
        cudaFuncSetAttribute(fine_match_kernel,
                             cudaFuncAttributeMaxDynamicSharedMemorySize,
                             SMEM_TOTAL);
        attr_done = true;
    }

    fine_match_kernel<<<GRID, 256, SMEM_TOTAL>>>(target, pos, out, n_points);
}